// round 6
// baseline (speedup 1.0000x reference)
#include <cuda_runtime.h>

#define NMAX   50000
#define EMAX   800000
#define EH     32
#define NET    3
#define CDIM   96      // NET*EH
#define ABDIM  192     // A(96) | B(96)

// ---- device scratch (static: no allocation allowed) ----
__device__ float g_AB[NMAX * ABDIM];        // per-node A|B precompute
__device__ float g_accum[NMAX * CDIM];      // scatter accumulators
__device__ float g_cnt[NMAX * NET];         // per (node, etype) counts
__device__ float g_H[NMAX * 64];            // layer-0 node output
__device__ float g_Wcat[128 * ABDIM];       // staged weights (max 24576 floats)

// ---------------------------------------------------------------------------
// Weight staging: eW (NET, 2K, EH) -> g_Wcat[K][192] with cols [A(96)|B(96)]
// ---------------------------------------------------------------------------
__global__ void prep_edge_w(const float* __restrict__ eW, int K) {
    int idx = blockIdx.x * blockDim.x + threadIdx.x;
    int tot = K * ABDIM;
    if (idx >= tot) return;
    int k = idx / ABDIM, c = idx - k * ABDIM;
    int half = c / CDIM;              // 0 = A (src part), 1 = B (dst part)
    int rem  = c % CDIM;
    int t = rem / EH, j = rem % EH;
    g_Wcat[idx] = eW[(size_t)t * (2 * K * EH) + (size_t)(half * K + k) * EH + j];
}

// nW (2, 96, OUTD) -> g_Wcat[96][2*OUTD] with cols [type0 | type1]
__global__ void prep_node_w(const float* __restrict__ nW, int OUTD) {
    int nc = 2 * OUTD;
    int tot = CDIM * nc;
    int idx = blockIdx.x * blockDim.x + threadIdx.x;
    if (idx >= tot) return;
    int k = idx / nc, c = idx - k * nc;
    int t = c / OUTD, j = c % OUTD;
    g_Wcat[idx] = nW[(size_t)t * CDIM * OUTD + (size_t)k * OUTD + j];
}

// ---------------------------------------------------------------------------
// FFMA2 register-tiled GEMM: out[n][·] = X[n][K] @ g_Wcat[K][NTOT], one
// CHUNK-wide column slab per blockIdx.y. 128 rows/block, 256 threads.
// Each warp: 16 rows (as 8 row-PAIRS packed in f32x2) x CHUNK cols (lanes).
//   FUSED=true: X is g_accum, divided by max(cnt,1) on load (mailbox mean),
//               and epilogue applies per-node-type select + bias + relu
//               (blockIdx.y == node type, CHUNK == OUTD).
// ---------------------------------------------------------------------------
template <int K, int NTOT, int CHUNK, bool FUSED>
__global__ __launch_bounds__(256) void gemm2(const float* __restrict__ X,
                                             const float* __restrict__ cnt,
                                             const int* __restrict__ nt,
                                             const float* __restrict__ nb,
                                             float* __restrict__ out, int n) {
    constexpr int CB = CHUNK / 32;
    __shared__ __align__(16) float Xs[32][130];   // [kk][row], +2 pad: 2-way STS, 8B-aligned pairs
    __shared__ float Ws[32][CHUNK];

    const int tid  = threadIdx.x;
    const int lane = tid & 31;
    const int warp = tid >> 5;
    const int base = blockIdx.x * 128;
    const int cb   = blockIdx.y * CHUNK;
    const int r0   = warp * 16;

    unsigned long long acc[8][CB];
#pragma unroll
    for (int ip = 0; ip < 8; ip++)
#pragma unroll
        for (int j = 0; j < CB; j++) acc[ip][j] = 0ull;

    for (int kc = 0; kc < K; kc += 32) {
        // X tile: transposed store Xs[kk][row]; coalesced global read.
#pragma unroll
        for (int i = 0; i < 16; i++) {
            int idx  = tid + i * 256;
            int kkf  = idx & 31;        // lane -> kk (contiguous global)
            int rowf = idx >> 5;        // warp-uniform row
            int row  = base + rowf;
            float v = 0.f;
            if (row < n) {
                v = X[(size_t)row * K + kc + kkf];
                if (FUSED) {
                    int t = (kc + kkf) >> 5;   // EH==32
                    v *= 1.0f / fmaxf(cnt[row * NET + t], 1.0f);
                }
            }
            Xs[kkf][rowf] = v;
        }
        // W tile (linear, coalesced, conflict-free)
#pragma unroll
        for (int i = 0; i < (32 * CHUNK) / 256; i++) {
            int idx = tid + i * 256;
            int kk = idx / CHUNK, c = idx - kk * CHUNK;
            Ws[kk][c] = g_Wcat[(size_t)(kc + kk) * NTOT + cb + c];
        }
        __syncthreads();

#pragma unroll
        for (int kk = 0; kk < 32; kk++) {
            unsigned long long x2[8];
#pragma unroll
            for (int ip = 0; ip < 8; ip++)   // broadcast LDS.64: rows (2ip, 2ip+1)
                x2[ip] = *(const unsigned long long*)&Xs[kk][r0 + 2 * ip];
            unsigned long long w2[CB];
#pragma unroll
            for (int j = 0; j < CB; j++) {
                float w = Ws[kk][lane + 32 * j];
                asm("mov.b64 %0, {%1, %1};" : "=l"(w2[j]) : "f"(w));
            }
#pragma unroll
            for (int ip = 0; ip < 8; ip++)
#pragma unroll
                for (int j = 0; j < CB; j++)
                    asm("fma.rn.f32x2 %0, %1, %2, %0;"
                        : "+l"(acc[ip][j]) : "l"(x2[ip]), "l"(w2[j]));
        }
        __syncthreads();
    }

    if (FUSED) {
        const int t = blockIdx.y;           // this column slab == node type t
        float bj[CB];
#pragma unroll
        for (int j = 0; j < CB; j++) bj[j] = nb[t * CHUNK + lane + 32 * j];
#pragma unroll
        for (int ip = 0; ip < 8; ip++) {
#pragma unroll
            for (int h = 0; h < 2; h++) {
                int row = base + r0 + 2 * ip + h;
                if (row < n && nt[row] == t) {
#pragma unroll
                    for (int j = 0; j < CB; j++) {
                        float v = ((const float*)&acc[ip][j])[h];
                        out[(size_t)row * CHUNK + lane + 32 * j] = fmaxf(v + bj[j], 0.f);
                    }
                }
            }
        }
    } else {
#pragma unroll
        for (int ip = 0; ip < 8; ip++) {
#pragma unroll
            for (int h = 0; h < 2; h++) {
                int row = base + r0 + 2 * ip + h;
                if (row < n) {
#pragma unroll
                    for (int j = 0; j < CB; j++)
                        out[(size_t)row * NTOT + cb + lane + 32 * j] =
                            ((const float*)&acc[ip][j])[h];
                }
            }
        }
    }
}

// ---------------------------------------------------------------------------
// Zero accumulators (graph replays re-execute everything)
// ---------------------------------------------------------------------------
__global__ void zero_kernel(int n) {
    int stride = gridDim.x * blockDim.x;
    int tid = blockIdx.x * blockDim.x + threadIdx.x;
    int tot4 = n * (CDIM / 4);
    float4 z = make_float4(0.f, 0.f, 0.f, 0.f);
    for (int i = tid; i < tot4; i += stride) ((float4*)g_accum)[i] = z;
    int totc = n * NET;
    for (int i = tid; i < totc; i += stride) g_cnt[i] = 0.f;
}

// ---------------------------------------------------------------------------
// Edge pass: 8 threads / edge, float4 lanes.
// m = relu(A[src,t] + B[dst,t] + bias[t]); red.v4 scatter into accum[dst].
// ---------------------------------------------------------------------------
__global__ __launch_bounds__(256) void edge_kernel(const int* __restrict__ ei,
                                                   const int* __restrict__ et,
                                                   const float* __restrict__ eb, int E) {
    int gid = blockIdx.x * blockDim.x + threadIdx.x;
    int e = gid >> 3;
    if (e >= E) return;
    int l = gid & 7;
    int src = ei[e], dst = ei[E + e], t = et[e];

    const float4 a  = *(const float4*)(g_AB + (size_t)src * ABDIM + t * EH + l * 4);
    const float4 b  = *(const float4*)(g_AB + (size_t)dst * ABDIM + CDIM + t * EH + l * 4);
    const float4 bi = *(const float4*)(eb + t * EH + l * 4);
    float4 m;
    m.x = fmaxf(a.x + b.x + bi.x, 0.f);
    m.y = fmaxf(a.y + b.y + bi.y, 0.f);
    m.z = fmaxf(a.z + b.z + bi.z, 0.f);
    m.w = fmaxf(a.w + b.w + bi.w, 0.f);

    float* p = g_accum + (size_t)dst * CDIM + t * EH + l * 4;
    asm volatile("red.global.add.v4.f32 [%0], {%1,%2,%3,%4};"
                 :: "l"(p), "f"(m.x), "f"(m.y), "f"(m.z), "f"(m.w) : "memory");
    if (l == 0) atomicAdd(g_cnt + (size_t)dst * NET + t, 1.0f);
}

// ---------------------------------------------------------------------------
extern "C" void kernel_launch(void* const* d_in, const int* in_sizes, int n_in,
                              void* d_out, int out_size) {
    const float* nf  = (const float*)d_in[0];
    const int*   ei  = (const int*)  d_in[1];
    const int*   et  = (const int*)  d_in[2];
    const int*   nt  = (const int*)  d_in[3];
    const float* eW0 = (const float*)d_in[4];
    const float* eb0 = (const float*)d_in[5];
    const float* nW0 = (const float*)d_in[6];
    const float* nb0 = (const float*)d_in[7];
    const float* eW1 = (const float*)d_in[8];
    const float* eb1 = (const float*)d_in[9];
    const float* nW1 = (const float*)d_in[10];
    const float* nb1 = (const float*)d_in[11];
    float* out = (float*)d_out;

    const int N = in_sizes[3];
    const int E = in_sizes[2];

    float *pAB, *pAcc, *pCnt, *pH;
    cudaGetSymbolAddress((void**)&pAB,  g_AB);
    cudaGetSymbolAddress((void**)&pAcc, g_accum);
    cudaGetSymbolAddress((void**)&pCnt, g_cnt);
    cudaGetSymbolAddress((void**)&pH,   g_H);

    const int nb128 = (N + 127) / 128;
    const dim3 g2(nb128, 2);
    const int gEdge = (E * 8 + 255) / 256;
    const int gMisc = 148 * 8;

    // ---------------- layer 0 (128 -> 64) ----------------
    prep_edge_w<<<(128 * ABDIM + 255) / 256, 256>>>(eW0, 128);
    gemm2<128, 192, 96, false><<<g2, 256>>>(nf, nullptr, nullptr, nullptr, pAB, N);
    zero_kernel<<<gMisc, 256>>>(N);
    edge_kernel<<<gEdge, 256>>>(ei, et, eb0, E);
    prep_node_w<<<(CDIM * 128 + 255) / 256, 256>>>(nW0, 64);
    gemm2<96, 128, 64, true><<<g2, 256>>>(pAcc, pCnt, nt, nb0, pH, N);

    // ---------------- layer 1 (64 -> 128) ----------------
    prep_edge_w<<<(64 * ABDIM + 255) / 256, 256>>>(eW1, 64);
    gemm2<64, 192, 96, false><<<g2, 256>>>(pH, nullptr, nullptr, nullptr, pAB, N);
    zero_kernel<<<gMisc, 256>>>(N);
    edge_kernel<<<gEdge, 256>>>(ei, et, eb1, E);
    prep_node_w<<<(CDIM * 256 + 255) / 256, 256>>>(nW1, 128);
    gemm2<96, 256, 128, true><<<g2, 256>>>(pAcc, pCnt, nt, nb1, out, N);
}

// round 10
// speedup vs baseline: 2.2617x; 2.2617x over previous
#include <cuda_runtime.h>
#include <cstdint>

#define NMAX   50000
#define EH     32
#define NET    3
#define CDIM   96      // NET*EH
#define ABDIM  192     // A(96) | B(96)

// ---- device scratch (static: no allocation allowed) ----
__device__ float g_AB[NMAX * ABDIM];     // per-node A|B precompute (edge bias folded into A)
__device__ float g_accum[NMAX * CDIM];   // scatter accumulators
__device__ float g_cnt[NMAX * NET];      // per (node, etype) counts (computed in layer 0)
__device__ float g_H[NMAX * 64];         // layer-0 node output
__device__ float g_Wstage[28672];        // weights staged as [kchunk][n][36] tf32

__device__ __forceinline__ float to_tf32(float x) {
    uint32_t r;
    asm("cvt.rna.tf32.f32 %0, %1;" : "=r"(r) : "f"(x));
    return __uint_as_float(r);
}

// ===========================================================================
// Weight staging: tf32-convert + reorganize into [kchunk][n][kk(36)] so the
// GEMM's W smem fill is a straight linear float4 copy.
// eW (NET, 2K, EH) -> B operand rows n in [0,192): n = half*96 + t*32 + j
// ===========================================================================
__global__ void prep_edge_w(const float* __restrict__ eW, int K) {
    int idx = blockIdx.x * blockDim.x + threadIdx.x;
    if (idx >= ABDIM * K) return;
    int n = idx / K, k = idx - n * K;
    int half = n / CDIM, rem = n % CDIM, t = rem / EH, j = rem % EH;
    float v = eW[(size_t)t * (2 * K * EH) + (size_t)(half * K + k) * EH + j];
    g_Wstage[(((k >> 5) * ABDIM) + n) * 36 + (k & 31)] = to_tf32(v);
}
// nW (2, 96, OUTD) -> rows n in [0, 2*OUTD): n = t*OUTD + j, K = 96
__global__ void prep_node_w(const float* __restrict__ nW, int OUTD) {
    int NR = 2 * OUTD;
    int idx = blockIdx.x * blockDim.x + threadIdx.x;
    if (idx >= NR * CDIM) return;
    int n = idx / CDIM, k = idx - n * CDIM;
    int t = n / OUTD, j = n - t * OUTD;
    float v = nW[(size_t)t * CDIM * OUTD + (size_t)k * OUTD + j];
    g_Wstage[(((k >> 5) * NR) + n) * 36 + (k & 31)] = to_tf32(v);
}

// ===========================================================================
// tf32 mma.sync GEMM: out[row][·] = X[row][K] @ W^T, 128 rows/block,
// CHUNK-wide column slab per blockIdx.y. 256 threads = 8 warps x 16 rows.
// Per warp: m16 x CHUNK via m16n8k8 tf32 mma, fp32 accumulate.
//   FUSED=false (AB gemm): slab y==0 adds edge bias (cols<96) and zeroes
//       g_accum rows (+ g_cnt when ZCNT) for the following edge pass.
//   FUSED=true (node gemm): X = g_accum / max(cnt,1) on load; slab y == node
//       type; epilogue does select + bias + relu into out[row][CHUNK].
// ===========================================================================
template <int K, int NTOT, int CHUNK, bool FUSED, bool ZCNT>
__global__ __launch_bounds__(256) void mma_gemm(const float* __restrict__ X,
                                                const float* __restrict__ cnt,
                                                const int* __restrict__ nt,
                                                const float* __restrict__ bias,
                                                float* __restrict__ out, int n) {
    constexpr int KC = 32;
    constexpr int NB = CHUNK / 8;
    __shared__ float Xs[128][36];
    __shared__ float Ws[CHUNK][36];

    const int tid = threadIdx.x;
    const int lane = tid & 31, wid = tid >> 5;
    const int gid = lane >> 2, tig = lane & 3;     // groupID, threadID-in-group
    const int base = blockIdx.x * 128;
    const int cb = blockIdx.y * CHUNK;             // global column base
    const int wr = wid * 16;                       // warp row base in tile

    float c[NB][4];
#pragma unroll
    for (int nb = 0; nb < NB; nb++)
#pragma unroll
        for (int q = 0; q < 4; q++) c[nb][q] = 0.f;

    for (int kc = 0; kc < K; kc += KC) {
        // ---- X tile [128 x 32], tf32-converted, row stride 36 ----
        const float inv = FUSED ? 0.f : 0.f;   // (placeholder, per-row below)
#pragma unroll
        for (int i = 0; i < 4; i++) {
            int idx = tid + i * 256;
            int row = idx >> 3, k4 = idx & 7;
            int grow = base + row;
            float4 v = make_float4(0.f, 0.f, 0.f, 0.f);
            if (grow < n) {
                v = *(const float4*)(X + (size_t)grow * K + kc + k4 * 4);
                if (FUSED) {
                    float s = 1.0f / fmaxf(cnt[grow * NET + (kc >> 5)], 1.0f);
                    v.x *= s; v.y *= s; v.z *= s; v.w *= s;
                }
            }
            float* p = &Xs[row][k4 * 4];
            p[0] = to_tf32(v.x); p[1] = to_tf32(v.y);
            p[2] = to_tf32(v.z); p[3] = to_tf32(v.w);
        }
        // ---- W tile: linear copy of pre-staged [CHUNK][36] slab ----
        {
            const float4* wsrc = (const float4*)(g_Wstage + (size_t)((kc >> 5) * NTOT + cb) * 36);
            float4* wdst = (float4*)&Ws[0][0];
            for (int idx = tid; idx < CHUNK * 9; idx += 256) wdst[idx] = wsrc[idx];
        }
        __syncthreads();

#pragma unroll
        for (int ks = 0; ks < KC / 8; ks++) {
            const int k0 = ks * 8;
            uint32_t a0 = __float_as_uint(Xs[wr + gid][k0 + tig]);
            uint32_t a1 = __float_as_uint(Xs[wr + gid + 8][k0 + tig]);
            uint32_t a2 = __float_as_uint(Xs[wr + gid][k0 + tig + 4]);
            uint32_t a3 = __float_as_uint(Xs[wr + gid + 8][k0 + tig + 4]);
#pragma unroll
            for (int nb = 0; nb < NB; nb++) {
                uint32_t b0 = __float_as_uint(Ws[nb * 8 + gid][k0 + tig]);
                uint32_t b1 = __float_as_uint(Ws[nb * 8 + gid][k0 + tig + 4]);
                asm volatile(
                    "mma.sync.aligned.m16n8k8.row.col.f32.tf32.tf32.f32 "
                    "{%0,%1,%2,%3}, {%4,%5,%6,%7}, {%8,%9}, {%0,%1,%2,%3};"
                    : "+f"(c[nb][0]), "+f"(c[nb][1]), "+f"(c[nb][2]), "+f"(c[nb][3])
                    : "r"(a0), "r"(a1), "r"(a2), "r"(a3), "r"(b0), "r"(b1));
            }
        }
        __syncthreads();
    }

    // ---- epilogue ----
    if (!FUSED) {
#pragma unroll
        for (int h = 0; h < 2; h++) {
            int row = base + wr + gid + 8 * h;
            if (row < n) {
#pragma unroll
                for (int nb = 0; nb < NB; nb++) {
                    int col = cb + nb * 8 + 2 * tig;
                    float2 v = make_float2(c[nb][2 * h], c[nb][2 * h + 1]);
                    if (blockIdx.y == 0) {          // A-part: fold edge bias
                        float2 b = *(const float2*)(bias + col);
                        v.x += b.x; v.y += b.y;
                    }
                    *(float2*)(out + (size_t)row * NTOT + col) = v;
                }
            }
        }
        // fused zeroing of scatter state for the edge pass (one slab does it)
        if (blockIdx.y == 0) {
            float4 z = make_float4(0.f, 0.f, 0.f, 0.f);
            for (int idx = lane; idx < 16 * 24; idx += 32) {
                int r = idx / 24, q = idx - r * 24;
                int row = base + wr + r;
                if (row < n) ((float4*)(g_accum + (size_t)row * CDIM))[q] = z;
            }
            if (ZCNT && lane < 16) {
                int row = base + wr + lane;
                if (row < n) {
                    g_cnt[row * NET] = 0.f;
                    g_cnt[row * NET + 1] = 0.f;
                    g_cnt[row * NET + 2] = 0.f;
                }
            }
        }
    } else {
        const int t = blockIdx.y;                   // slab == node type
#pragma unroll
        for (int h = 0; h < 2; h++) {
            int row = base + wr + gid + 8 * h;
            if (row < n && nt[row] == t) {
#pragma unroll
                for (int nb = 0; nb < NB; nb++) {
                    int col = nb * 8 + 2 * tig;
                    float2 b = *(const float2*)(bias + t * CHUNK + col);
                    float2 v;
                    v.x = fmaxf(c[nb][2 * h] + b.x, 0.f);
                    v.y = fmaxf(c[nb][2 * h + 1] + b.y, 0.f);
                    *(float2*)(out + (size_t)row * CHUNK + col) = v;
                }
            }
        }
    }
}

// ===========================================================================
// Edge pass: 8 threads / edge, float4 lanes. Bias already folded into A.
// m = relu(A'[src,t] + B[dst,t]); red.v4 scatter into accum[dst].
// ===========================================================================
template <bool COUNT>
__global__ __launch_bounds__(256) void edge_kernel(const int* __restrict__ ei,
                                                   const int* __restrict__ et, int E) {
    int gid = blockIdx.x * blockDim.x + threadIdx.x;
    int e = gid >> 3;
    if (e >= E) return;
    int l = gid & 7;
    int src = ei[e], dst = ei[E + e], t = et[e];

    const float4 a = *(const float4*)(g_AB + (size_t)src * ABDIM + t * EH + l * 4);
    const float4 b = *(const float4*)(g_AB + (size_t)dst * ABDIM + CDIM + t * EH + l * 4);
    float4 m;
    m.x = fmaxf(a.x + b.x, 0.f);
    m.y = fmaxf(a.y + b.y, 0.f);
    m.z = fmaxf(a.z + b.z, 0.f);
    m.w = fmaxf(a.w + b.w, 0.f);

    float* p = g_accum + (size_t)dst * CDIM + t * EH + l * 4;
    asm volatile("red.global.add.v4.f32 [%0], {%1,%2,%3,%4};"
                 :: "l"(p), "f"(m.x), "f"(m.y), "f"(m.z), "f"(m.w) : "memory");
    if (COUNT && l == 0) atomicAdd(g_cnt + (size_t)dst * NET + t, 1.0f);
}

// ===========================================================================
extern "C" void kernel_launch(void* const* d_in, const int* in_sizes, int n_in,
                              void* d_out, int out_size) {
    const float* nf  = (const float*)d_in[0];
    const int*   ei  = (const int*)  d_in[1];
    const int*   et  = (const int*)  d_in[2];
    const int*   nt  = (const int*)  d_in[3];
    const float* eW0 = (const float*)d_in[4];
    const float* eb0 = (const float*)d_in[5];
    const float* nW0 = (const float*)d_in[6];
    const float* nb0 = (const float*)d_in[7];
    const float* eW1 = (const float*)d_in[8];
    const float* eb1 = (const float*)d_in[9];
    const float* nW1 = (const float*)d_in[10];
    const float* nb1 = (const float*)d_in[11];
    float* out = (float*)d_out;

    const int N = in_sizes[3];
    const int E = in_sizes[2];

    float *pAB, *pAcc, *pCnt, *pH;
    cudaGetSymbolAddress((void**)&pAB,  g_AB);
    cudaGetSymbolAddress((void**)&pAcc, g_accum);
    cudaGetSymbolAddress((void**)&pCnt, g_cnt);
    cudaGetSymbolAddress((void**)&pH,   g_H);

    const int nb128 = (N + 127) / 128;
    const dim3 g2(nb128, 2);
    const int gEdge = (E * 8 + 255) / 256;

    // ---------------- layer 0 (128 -> 64) ----------------
    prep_edge_w<<<(ABDIM * 128 + 255) / 256, 256>>>(eW0, 128);
    mma_gemm<128, 192, 96, false, true><<<g2, 256>>>(nf, nullptr, nullptr, eb0, pAB, N);
    edge_kernel<true><<<gEdge, 256>>>(ei, et, E);
    prep_node_w<<<(128 * CDIM + 255) / 256, 256>>>(nW0, 64);
    mma_gemm<96, 128, 64, true, false><<<g2, 256>>>(pAcc, pCnt, nt, nb0, pH, N);

    // ---------------- layer 1 (64 -> 128) ----------------
    prep_edge_w<<<(ABDIM * 64 + 255) / 256, 256>>>(eW1, 64);
    mma_gemm<64, 192, 96, false, false><<<g2, 256>>>(pH, nullptr, nullptr, eb1, pAB, N);
    edge_kernel<false><<<gEdge, 256>>>(ei, et, E);
    prep_node_w<<<(256 * CDIM + 255) / 256, 256>>>(nW1, 128);
    mma_gemm<96, 256, 128, true, false><<<g2, 256>>>(pAcc, pCnt, nt, nb1, out, N);
}

// round 11
// speedup vs baseline: 2.7708x; 1.2251x over previous
#include <cuda_runtime.h>
#include <cuda_fp16.h>
#include <cstdint>

#define NMAX   50000
#define EH     32
#define NET    3
#define CDIM   96      // NET*EH
#define ABDIM  192     // A(96) | B(96)

// ---- device scratch (static: no allocation allowed) ----
__device__ float  g_AB[NMAX * ABDIM];    // per-node A|B precompute (edge bias folded into A)
__device__ float  g_accum[NMAX * CDIM];  // scatter accumulators
__device__ float  g_cnt[NMAX * NET];     // per (node, etype) counts (computed in layer 0)
__device__ float  g_H[NMAX * 64];        // layer-0 node output
__device__ __half g_Wstage[98304];       // all 4 weight sets staged as [kchunk][n][40] fp16

// stage offsets (in halfs)
#define OFF_E0 0        // 4 kchunks * 192 * 40 = 30720
#define OFF_N0 30720    // 3 * 128 * 40        = 15360
#define OFF_E1 46080    // 2 * 192 * 40        = 15360
#define OFF_N1 61440    // 3 * 256 * 40        = 30720

// ===========================================================================
// Combined weight staging: all four weight tensors -> fp16, laid out
// [kchunk][n][40] so each GEMM's W smem fill is a linear int4 copy.
// ===========================================================================
__device__ __forceinline__ void stage_edge(const float* eW, int K, int off, int q) {
    int n = q / K, k = q - n * K;
    int half_ = n / CDIM, rem = n % CDIM, t = rem / EH, j = rem % EH;
    float v = eW[(size_t)t * (2 * K * EH) + (size_t)(half_ * K + k) * EH + j];
    g_Wstage[off + (((k >> 5) * ABDIM) + n) * 40 + (k & 31)] = __float2half_rn(v);
}
__device__ __forceinline__ void stage_node(const float* nW, int OUTD, int off, int q) {
    int NR = 2 * OUTD;
    int n = q / CDIM, k = q - n * CDIM;
    int t = n / OUTD, j = n - t * OUTD;
    float v = nW[(size_t)t * CDIM * OUTD + (size_t)k * OUTD + j];
    g_Wstage[off + (((k >> 5) * NR) + n) * 40 + (k & 31)] = __float2half_rn(v);
}
__global__ void prep_all(const float* __restrict__ eW0, const float* __restrict__ nW0,
                         const float* __restrict__ eW1, const float* __restrict__ nW1) {
    int idx = blockIdx.x * blockDim.x + threadIdx.x;
    if (idx < 24576)                  stage_edge(eW0, 128, OFF_E0, idx);
    else if (idx < 24576 + 12288)     stage_node(nW0,  64, OFF_N0, idx - 24576);
    else if (idx < 36864 + 12288)     stage_edge(eW1,  64, OFF_E1, idx - 36864);
    else if (idx < 49152 + 24576)     stage_node(nW1, 128, OFF_N1, idx - 49152);
}

// ===========================================================================
// fp16 mma.sync GEMM: out[row][·] = X[row][K] @ W^T, 128 rows/block,
// CHUNK-wide column slab per blockIdx.y. 256 threads = 8 warps x 16 rows.
// m16n8k16.f32.f16.f16.f32, fp32 accumulate, fp32 epilogue.
//   FUSED=false (AB gemm): slab y==0 adds edge bias (cols<96) and zeroes
//       g_accum rows (+ g_cnt when ZCNT) for the following edge pass.
//   FUSED=true (node gemm): X = g_accum / max(cnt,1) on load; slab y == node
//       type; epilogue does select + bias + relu into out[row][CHUNK].
// ===========================================================================
template <int K, int NTOT, int CHUNK, int WOFF, bool FUSED, bool ZCNT>
__global__ __launch_bounds__(256) void mma_gemm(const float* __restrict__ X,
                                                const float* __restrict__ cnt,
                                                const int* __restrict__ nt,
                                                const float* __restrict__ bias,
                                                float* __restrict__ out, int n) {
    constexpr int NB = CHUNK / 8;
    __shared__ __half Xs[128][40];
    __shared__ __half Ws[CHUNK][40];

    const int tid = threadIdx.x;
    const int lane = tid & 31, wid = tid >> 5;
    const int gid = lane >> 2, tig = lane & 3;     // groupID, threadID-in-group
    const int base = blockIdx.x * 128;
    const int cb = blockIdx.y * CHUNK;             // global column base
    const int wr = wid * 16;                       // warp row base in tile

    float c[NB][4];
#pragma unroll
    for (int nb = 0; nb < NB; nb++)
#pragma unroll
        for (int q = 0; q < 4; q++) c[nb][q] = 0.f;

    for (int kc = 0; kc < K; kc += 32) {
        // ---- X tile [128 x 32] fp32 -> fp16, row stride 40 halfs ----
#pragma unroll
        for (int i = 0; i < 4; i++) {
            int idx = tid + i * 256;
            int row = idx >> 3, k4 = idx & 7;
            int grow = base + row;
            float4 v = make_float4(0.f, 0.f, 0.f, 0.f);
            if (grow < n) {
                v = *(const float4*)(X + (size_t)grow * K + kc + k4 * 4);
                if (FUSED) {
                    float s = 1.0f / fmaxf(cnt[grow * NET + (kc >> 5)], 1.0f);
                    v.x *= s; v.y *= s; v.z *= s; v.w *= s;
                }
            }
            *(half2*)&Xs[row][k4 * 4]     = __floats2half2_rn(v.x, v.y);
            *(half2*)&Xs[row][k4 * 4 + 2] = __floats2half2_rn(v.z, v.w);
        }
        // ---- W tile: linear int4 copy of pre-staged [CHUNK][40] slab ----
        {
            const int4* wsrc = (const int4*)(g_Wstage + WOFF + (size_t)((kc >> 5) * NTOT + cb) * 40);
            int4* wdst = (int4*)&Ws[0][0];
#pragma unroll
            for (int i = 0; i < (CHUNK * 5 + 255) / 256; i++) {
                int idx = tid + i * 256;
                if (idx < CHUNK * 5) wdst[idx] = wsrc[idx];
            }
        }
        __syncthreads();

#pragma unroll
        for (int ks = 0; ks < 2; ks++) {
            const int k0 = ks * 16;
            uint32_t a0 = *(const uint32_t*)&Xs[wr + gid][k0 + 2 * tig];
            uint32_t a1 = *(const uint32_t*)&Xs[wr + gid + 8][k0 + 2 * tig];
            uint32_t a2 = *(const uint32_t*)&Xs[wr + gid][k0 + 2 * tig + 8];
            uint32_t a3 = *(const uint32_t*)&Xs[wr + gid + 8][k0 + 2 * tig + 8];
#pragma unroll
            for (int nb = 0; nb < NB; nb++) {
                uint32_t b0 = *(const uint32_t*)&Ws[nb * 8 + gid][k0 + 2 * tig];
                uint32_t b1 = *(const uint32_t*)&Ws[nb * 8 + gid][k0 + 2 * tig + 8];
                asm volatile(
                    "mma.sync.aligned.m16n8k16.row.col.f32.f16.f16.f32 "
                    "{%0,%1,%2,%3}, {%4,%5,%6,%7}, {%8,%9}, {%0,%1,%2,%3};"
                    : "+f"(c[nb][0]), "+f"(c[nb][1]), "+f"(c[nb][2]), "+f"(c[nb][3])
                    : "r"(a0), "r"(a1), "r"(a2), "r"(a3), "r"(b0), "r"(b1));
            }
        }
        __syncthreads();
    }

    // ---- epilogue (fp32) ----
    if (!FUSED) {
#pragma unroll
        for (int h = 0; h < 2; h++) {
            int row = base + wr + gid + 8 * h;
            if (row < n) {
#pragma unroll
                for (int nb = 0; nb < NB; nb++) {
                    int col = cb + nb * 8 + 2 * tig;
                    float2 v = make_float2(c[nb][2 * h], c[nb][2 * h + 1]);
                    if (blockIdx.y == 0) {          // A-part: fold edge bias
                        float2 b = *(const float2*)(bias + col);
                        v.x += b.x; v.y += b.y;
                    }
                    *(float2*)(out + (size_t)row * NTOT + col) = v;
                }
            }
        }
        // fused zeroing of scatter state for the edge pass (slab 0 does it)
        if (blockIdx.y == 0) {
            float4 z = make_float4(0.f, 0.f, 0.f, 0.f);
            for (int idx = lane; idx < 16 * 24; idx += 32) {
                int r = idx / 24, q = idx - r * 24;
                int row = base + wr + r;
                if (row < n) ((float4*)(g_accum + (size_t)row * CDIM))[q] = z;
            }
            if (ZCNT && lane < 16) {
                int row = base + wr + lane;
                if (row < n) {
                    g_cnt[row * NET] = 0.f;
                    g_cnt[row * NET + 1] = 0.f;
                    g_cnt[row * NET + 2] = 0.f;
                }
            }
        }
    } else {
        const int t = blockIdx.y;                   // slab == node type
#pragma unroll
        for (int h = 0; h < 2; h++) {
            int row = base + wr + gid + 8 * h;
            if (row < n && nt[row] == t) {
#pragma unroll
                for (int nb = 0; nb < NB; nb++) {
                    int col = nb * 8 + 2 * tig;
                    float2 b = *(const float2*)(bias + t * CHUNK + col);
                    float2 v;
                    v.x = fmaxf(c[nb][2 * h] + b.x, 0.f);
                    v.y = fmaxf(c[nb][2 * h + 1] + b.y, 0.f);
                    *(float2*)(out + (size_t)row * CHUNK + col) = v;
                }
            }
        }
    }
}

// ===========================================================================
// Edge pass: 8 threads / edge, float4 lanes. Bias already folded into A.
// m = relu(A'[src,t] + B[dst,t]); red.v4 scatter into accum[dst].
// ===========================================================================
template <bool COUNT>
__global__ __launch_bounds__(256) void edge_kernel(const int* __restrict__ ei,
                                                   const int* __restrict__ et, int E) {
    int gid = blockIdx.x * blockDim.x + threadIdx.x;
    int e = gid >> 3;
    if (e >= E) return;
    int l = gid & 7;
    int src = ei[e], dst = ei[E + e], t = et[e];

    const float4 a = *(const float4*)(g_AB + (size_t)src * ABDIM + t * EH + l * 4);
    const float4 b = *(const float4*)(g_AB + (size_t)dst * ABDIM + CDIM + t * EH + l * 4);
    float4 m;
    m.x = fmaxf(a.x + b.x, 0.f);
    m.y = fmaxf(a.y + b.y, 0.f);
    m.z = fmaxf(a.z + b.z, 0.f);
    m.w = fmaxf(a.w + b.w, 0.f);

    float* p = g_accum + (size_t)dst * CDIM + t * EH + l * 4;
    asm volatile("red.global.add.v4.f32 [%0], {%1,%2,%3,%4};"
                 :: "l"(p), "f"(m.x), "f"(m.y), "f"(m.z), "f"(m.w) : "memory");
    if (COUNT && l == 0) atomicAdd(g_cnt + (size_t)dst * NET + t, 1.0f);
}

// ===========================================================================
extern "C" void kernel_launch(void* const* d_in, const int* in_sizes, int n_in,
                              void* d_out, int out_size) {
    const float* nf  = (const float*)d_in[0];
    const int*   ei  = (const int*)  d_in[1];
    const int*   et  = (const int*)  d_in[2];
    const int*   nt  = (const int*)  d_in[3];
    const float* eW0 = (const float*)d_in[4];
    const float* eb0 = (const float*)d_in[5];
    const float* nW0 = (const float*)d_in[6];
    const float* nb0 = (const float*)d_in[7];
    const float* eW1 = (const float*)d_in[8];
    const float* eb1 = (const float*)d_in[9];
    const float* nW1 = (const float*)d_in[10];
    const float* nb1 = (const float*)d_in[11];
    float* out = (float*)d_out;

    const int N = in_sizes[3];
    const int E = in_sizes[2];

    float *pAB, *pAcc, *pCnt, *pH;
    cudaGetSymbolAddress((void**)&pAB,  g_AB);
    cudaGetSymbolAddress((void**)&pAcc, g_accum);
    cudaGetSymbolAddress((void**)&pCnt, g_cnt);
    cudaGetSymbolAddress((void**)&pH,   g_H);

    const int nb128 = (N + 127) / 128;
    const dim3 g2(nb128, 2);
    const int gEdge = (E * 8 + 255) / 256;

    // one staging kernel for all four weight tensors
    prep_all<<<(73728 + 255) / 256, 256>>>(eW0, nW0, eW1, nW1);

    // ---------------- layer 0 (128 -> 64) ----------------
    mma_gemm<128, 192, 96, OFF_E0, false, true><<<g2, 256>>>(nf, nullptr, nullptr, eb0, pAB, N);
    edge_kernel<true><<<gEdge, 256>>>(ei, et, E);
    mma_gemm<96, 128, 64, OFF_N0, true, false><<<g2, 256>>>(pAcc, pCnt, nt, nb0, pH, N);

    // ---------------- layer 1 (64 -> 128) ----------------
    mma_gemm<64, 192, 96, OFF_E1, false, false><<<g2, 256>>>(pH, nullptr, nullptr, eb1, pAB, N);
    edge_kernel<false><<<gEdge, 256>>>(ei, et, E);
    mma_gemm<96, 256, 128, OFF_N1, true, false><<<g2, 256>>>(pAcc, pCnt, nt, nb1, out, N);
}